// round 3
// baseline (speedup 1.0000x reference)
#include <cuda_runtime.h>
#include <math.h>
#include <stdint.h>

// Problem constants
#define CL 4
#define CDM 768
#define CDI 1536
#define CDS 16
#define CDR 48
#define CKC 4
#define CV 32000
#define CB 2
#define CS 2048
#define CBS (CB*CS)          // 4096 tokens
#define CDBC 80              // DR + 2*DS

// ---------------- scratch arena (no allocations allowed) ----------------
#define SZ_H   ((size_t)CBS*CDM)
#define SZ_XZ  ((size_t)CBS*2*CDI)
#define SZ_XC  ((size_t)CBS*CDI)
#define SZ_DBC ((size_t)CBS*CDBC)

#define O_H0   ((size_t)0)
#define O_H1   (O_H0 + SZ_H)
#define O_XN0  (O_H1 + SZ_H)
#define O_XN1  (O_XN0 + SZ_H)
#define O_XZ0  (O_XN1 + SZ_H)
#define O_XZ1  (O_XZ0 + SZ_XZ)
#define O_XC0  (O_XZ1 + SZ_XZ)
#define O_XC1  (O_XC0 + SZ_XC)
#define O_DBC0 (O_XC1 + SZ_XC)
#define O_DBC1 (O_DBC0 + SZ_DBC)
#define O_DT0  (O_DBC1 + SZ_DBC)
#define O_DT1  (O_DT0 + SZ_XC)
#define O_Y0   (O_DT1 + SZ_XC)
#define O_Y1   (O_Y0 + SZ_XC)
#define O_COMB (O_Y1 + SZ_XC)
#define O_NLL  (O_COMB + (size_t)CBS*2*CDM)
#define O_VAL  (O_NLL + CBS)
#define ARENA_TOTAL (O_VAL + CBS)

__device__ float g_arena[ARENA_TOTAL];

// ---------------- PTX helpers ----------------
__device__ __forceinline__ float to_tf32(float x) {
    float r;
    asm("cvt.rna.tf32.f32 %0, %1;" : "=f"(r) : "f"(x));
    return r;
}

__device__ __forceinline__ void mma_tf32(float* d, const uint32_t* a, const uint32_t* b) {
    asm volatile(
        "mma.sync.aligned.m16n8k8.row.col.f32.tf32.tf32.f32 "
        "{%0,%1,%2,%3}, {%4,%5,%6,%7}, {%8,%9}, {%0,%1,%2,%3};"
        : "+f"(d[0]), "+f"(d[1]), "+f"(d[2]), "+f"(d[3])
        : "r"(a[0]), "r"(a[1]), "r"(a[2]), "r"(a[3]), "r"(b[0]), "r"(b[1]));
}

// ---------------- tensor-core GEMM (3xTF32, pre-split smem planes)
// C[M,N] (+)= A[M,K(lda)] * B[N,K]^T
// M multiple of 128; K multiple of 16; N arbitrary.
#define BM 128
#define BN 128
#define BKK 16
#define APITCH 20   // floats; 20g+tg mod 32 hits 32 distinct banks -> conflict-free

__global__ __launch_bounds__(256)
void gemm_tc(const float* __restrict__ A, int lda,
             const float* __restrict__ Bw,
             float* __restrict__ C,
             int M, int N, int K,
             const float* __restrict__ bias, int act, int acc)
{
    __shared__ float Ah[BM * APITCH];
    __shared__ float Al[BM * APITCH];
    __shared__ float Bh[BN * APITCH];
    __shared__ float Bl[BN * APITCH];

    const int tid = threadIdx.x;
    const int wid = tid >> 5, lane = tid & 31;
    const int g = lane >> 2, tg = lane & 3;
    const int warp_m = (wid & 1) * 64;
    const int warp_n = (wid >> 1) * 32;
    const int m0 = blockIdx.y * BM;
    const int n0 = blockIdx.x * BN;

    float accr[4][4][4];
#pragma unroll
    for (int i = 0; i < 4; i++)
#pragma unroll
        for (int j = 0; j < 4; j++)
#pragma unroll
            for (int r = 0; r < 4; r++) accr[i][j][r] = 0.f;

    const int nIter = K / BKK;

    // per-thread staging coords: 2 chunks of 4 floats each for A and B
    const int cm0 = (tid * 2) >> 2;            // row for chunk 0
    const int ck0 = ((tid * 2) & 3) * 4;       // k-offset for chunk 0
    const int cm1 = (tid * 2 + 1) >> 2;
    const int ck1 = ((tid * 2 + 1) & 3) * 4;

    const float4 zero4 = make_float4(0.f, 0.f, 0.f, 0.f);
    float4 ra0, ra1, rb0, rb1;

#define LOADG(it) do {                                                          \
    int k0p = (it) * BKK;                                                       \
    ra0 = *(const float4*)(A + (size_t)(m0 + cm0) * lda + k0p + ck0);           \
    ra1 = *(const float4*)(A + (size_t)(m0 + cm1) * lda + k0p + ck1);           \
    rb0 = (n0 + cm0) < N ? *(const float4*)(Bw + (size_t)(n0 + cm0) * K + k0p + ck0) : zero4; \
    rb1 = (n0 + cm1) < N ? *(const float4*)(Bw + (size_t)(n0 + cm1) * K + k0p + ck1) : zero4; \
} while (0)

#define SPLIT_STORE(v, Hp, Lp, off) do {                                        \
    float4 _h, _l;                                                              \
    _h.x = to_tf32((v).x); _l.x = to_tf32((v).x - _h.x);                        \
    _h.y = to_tf32((v).y); _l.y = to_tf32((v).y - _h.y);                        \
    _h.z = to_tf32((v).z); _l.z = to_tf32((v).z - _h.z);                        \
    _h.w = to_tf32((v).w); _l.w = to_tf32((v).w - _h.w);                        \
    *(float4*)&(Hp)[off] = _h; *(float4*)&(Lp)[off] = _l;                       \
} while (0)

    LOADG(0);

    for (int it = 0; it < nIter; it++) {
        __syncthreads();   // previous compute done before overwrite
        SPLIT_STORE(ra0, Ah, Al, cm0 * APITCH + ck0);
        SPLIT_STORE(ra1, Ah, Al, cm1 * APITCH + ck1);
        SPLIT_STORE(rb0, Bh, Bl, cm0 * APITCH + ck0);
        SPLIT_STORE(rb1, Bh, Bl, cm1 * APITCH + ck1);
        __syncthreads();

        if (it + 1 < nIter) LOADG(it + 1);

#pragma unroll
        for (int ks = 0; ks < BKK; ks += 8) {
            uint32_t ahi[4][4], alo[4][4], bhi[4][2], blo[4][2];
#pragma unroll
            for (int mt = 0; mt < 4; mt++) {
                int r0 = (warp_m + mt * 16 + g) * APITCH + ks + tg;
                int r1 = (warp_m + mt * 16 + g + 8) * APITCH + ks + tg;
                ahi[mt][0] = __float_as_uint(Ah[r0]);
                ahi[mt][1] = __float_as_uint(Ah[r1]);
                ahi[mt][2] = __float_as_uint(Ah[r0 + 4]);
                ahi[mt][3] = __float_as_uint(Ah[r1 + 4]);
                alo[mt][0] = __float_as_uint(Al[r0]);
                alo[mt][1] = __float_as_uint(Al[r1]);
                alo[mt][2] = __float_as_uint(Al[r0 + 4]);
                alo[mt][3] = __float_as_uint(Al[r1 + 4]);
            }
#pragma unroll
            for (int nt = 0; nt < 4; nt++) {
                int c0 = (warp_n + nt * 8 + g) * APITCH + ks + tg;
                bhi[nt][0] = __float_as_uint(Bh[c0]);
                bhi[nt][1] = __float_as_uint(Bh[c0 + 4]);
                blo[nt][0] = __float_as_uint(Bl[c0]);
                blo[nt][1] = __float_as_uint(Bl[c0 + 4]);
            }
#pragma unroll
            for (int mt = 0; mt < 4; mt++)
#pragma unroll
                for (int nt = 0; nt < 4; nt++) {
                    mma_tf32(accr[mt][nt], ahi[mt], bhi[nt]);
                    mma_tf32(accr[mt][nt], ahi[mt], blo[nt]);
                    mma_tf32(accr[mt][nt], alo[mt], bhi[nt]);
                }
        }
    }

    // epilogue
#pragma unroll
    for (int mt = 0; mt < 4; mt++) {
        int row0 = m0 + warp_m + mt * 16 + g;
#pragma unroll
        for (int nt = 0; nt < 4; nt++) {
            int col0 = n0 + warp_n + nt * 8 + tg * 2;
#pragma unroll
            for (int half = 0; half < 2; half++) {
                int m = row0 + half * 8;
#pragma unroll
                for (int j = 0; j < 2; j++) {
                    int n = col0 + j;
                    if (n < N) {
                        float v = accr[mt][nt][half * 2 + j];
                        if (bias) v += bias[n];
                        if (act == 1) v = (v > 20.f) ? v : log1pf(expf(v));
                        size_t off = (size_t)m * N + n;
                        if (acc) v += C[off];
                        C[off] = v;
                    }
                }
            }
        }
    }
}

// ---------------- embedding (with optional time flip for bw) ----------------
__global__ void embed_kernel(const int* __restrict__ ids,
                             const float* __restrict__ emb,
                             float* __restrict__ h, int flip)
{
    size_t idx = (size_t)blockIdx.x * blockDim.x + threadIdx.x;
    if (idx >= (size_t)CBS * CDM) return;
    int r = (int)(idx / CDM);
    int c = (int)(idx % CDM);
    int b = r / CS, t = r % CS;
    int tt = flip ? (CS - 1 - t) : t;
    int id = ids[b * CS + tt];
    h[idx] = emb[(size_t)id * CDM + c];
}

// ---------------- RMSNorm (one block per token) ----------------
__global__ void rms_kernel(const float* __restrict__ x,
                           const float* __restrict__ w,
                           float* __restrict__ out)
{
    int r = blockIdx.x;
    const float* xr = x + (size_t)r * CDM;
    float s = 0.f;
    for (int i = threadIdx.x; i < CDM; i += blockDim.x) { float v = xr[i]; s += v * v; }
    __shared__ float sm[8];
    __shared__ float scale_sh;
    for (int o = 16; o > 0; o >>= 1) s += __shfl_xor_sync(0xffffffffu, s, o);
    if ((threadIdx.x & 31) == 0) sm[threadIdx.x >> 5] = s;
    __syncthreads();
    if (threadIdx.x == 0) {
        float t = 0.f;
        for (int i = 0; i < 8; i++) t += sm[i];
        scale_sh = rsqrtf(t / CDM + 1e-5f);
    }
    __syncthreads();
    float sc = scale_sh;
    for (int i = threadIdx.x; i < CDM; i += blockDim.x)
        out[(size_t)r * CDM + i] = xr[i] * sc * w[i];
}

// ---------------- causal conv (k=4) + bias + silu ----------------
__global__ void conv_kernel(const float* __restrict__ xz,
                            const float* __restrict__ convw,
                            const float* __restrict__ convb,
                            float* __restrict__ xc)
{
    size_t idx = (size_t)blockIdx.x * blockDim.x + threadIdx.x;
    if (idx >= (size_t)CBS * CDI) return;
    int r = (int)(idx / CDI);
    int d = (int)(idx % CDI);
    int t = r % CS;
    float acc = convb[d];
#pragma unroll
    for (int k = 0; k < CKC; k++) {
        int tt = t - (CKC - 1) + k;
        if (tt >= 0)
            acc += xz[(size_t)(r - (CKC - 1) + k) * (2 * CDI) + d] * convw[d * CKC + k];
    }
    float sg = 1.f / (1.f + expf(-acc));
    xc[idx] = acc * sg;
}

// ---------------- selective scan: 16 lanes per (b,d) channel ----------------
__global__ void scan_kernel(const float* __restrict__ dt,
                            const float* __restrict__ xc,
                            const float* __restrict__ dbc,
                            const float* __restrict__ Alog_l,
                            float* __restrict__ y)
{
    int gid = blockIdx.x * blockDim.x + threadIdx.x;
    int lane = gid & 15;
    int grp = gid >> 4;
    if (grp >= CB * CDI) return;
    int d = grp % CDI;
    int b = grp / CDI;
    float Aval = -expf(Alog_l[d * CDS + lane]);
    float h = 0.f;
    const float* dtp = dt + (size_t)b * CS * CDI + d;
    const float* xp  = xc + (size_t)b * CS * CDI + d;
    const float* bp  = dbc + (size_t)b * CS * CDBC + CDR + lane;
    const float* cp  = dbc + (size_t)b * CS * CDBC + CDR + CDS + lane;
    float* yp        = y + (size_t)b * CS * CDI + d;
    for (int t = 0; t < CS; t++) {
        float dtv = dtp[(size_t)t * CDI];
        float xv  = xp[(size_t)t * CDI];
        float Bv  = bp[(size_t)t * CDBC];
        float Cv  = cp[(size_t)t * CDBC];
        float a = expf(dtv * Aval);
        h = a * h + (dtv * xv) * Bv;
        float contrib = h * Cv;
        contrib += __shfl_xor_sync(0xffffffffu, contrib, 8);
        contrib += __shfl_xor_sync(0xffffffffu, contrib, 4);
        contrib += __shfl_xor_sync(0xffffffffu, contrib, 2);
        contrib += __shfl_xor_sync(0xffffffffu, contrib, 1);
        if (lane == 0) yp[(size_t)t * CDI] = contrib;
    }
}

// ---------------- gate: g = (y + Dp*xc) * silu(z) ----------------
__global__ void gate_kernel(float* __restrict__ y,
                            const float* __restrict__ xc,
                            const float* __restrict__ xz,
                            const float* __restrict__ Dp)
{
    size_t idx = (size_t)blockIdx.x * blockDim.x + threadIdx.x;
    if (idx >= (size_t)CBS * CDI) return;
    int r = (int)(idx / CDI);
    int d = (int)(idx % CDI);
    float z = xz[(size_t)r * (2 * CDI) + CDI + d];
    float sz = z / (1.f + expf(-z));
    y[idx] = (y[idx] + Dp[d] * xc[idx]) * sz;
}

// ---------------- final rms + concat (bw flipped back) ----------------
__global__ void combined_kernel(const float* __restrict__ hf,
                                const float* __restrict__ hb,
                                const float* __restrict__ wf,
                                const float* __restrict__ wb,
                                float* __restrict__ comb)
{
    int r = blockIdx.x;
    int b = r / CS, t = r % CS;
    const float* xf = hf + (size_t)r * CDM;
    const float* xb = hb + ((size_t)b * CS + (CS - 1 - t)) * CDM;
    __shared__ float sm[8];
    __shared__ float sc_sh;

    float s = 0.f;
    for (int i = threadIdx.x; i < CDM; i += blockDim.x) { float v = xf[i]; s += v * v; }
    for (int o = 16; o > 0; o >>= 1) s += __shfl_xor_sync(0xffffffffu, s, o);
    if ((threadIdx.x & 31) == 0) sm[threadIdx.x >> 5] = s;
    __syncthreads();
    if (threadIdx.x == 0) {
        float tt = 0.f; for (int i = 0; i < 8; i++) tt += sm[i];
        sc_sh = rsqrtf(tt / CDM + 1e-5f);
    }
    __syncthreads();
    float sc = sc_sh;
    for (int i = threadIdx.x; i < CDM; i += blockDim.x)
        comb[(size_t)r * (2 * CDM) + i] = xf[i] * sc * wf[i];
    __syncthreads();

    s = 0.f;
    for (int i = threadIdx.x; i < CDM; i += blockDim.x) { float v = xb[i]; s += v * v; }
    for (int o = 16; o > 0; o >>= 1) s += __shfl_xor_sync(0xffffffffu, s, o);
    if ((threadIdx.x & 31) == 0) sm[threadIdx.x >> 5] = s;
    __syncthreads();
    if (threadIdx.x == 0) {
        float tt = 0.f; for (int i = 0; i < 8; i++) tt += sm[i];
        sc_sh = rsqrtf(tt / CDM + 1e-5f);
    }
    __syncthreads();
    sc = sc_sh;
    for (int i = threadIdx.x; i < CDM; i += blockDim.x)
        comb[(size_t)r * (2 * CDM) + CDM + i] = xb[i] * sc * wb[i];
}

// ---------------- per-row cross-entropy ----------------
__global__ void loss_row_kernel(const float* __restrict__ logits,
                                const int* __restrict__ labels,
                                float* __restrict__ nll,
                                float* __restrict__ valid)
{
    int r = blockIdx.x;
    const float* row = logits + (size_t)r * CV;
    __shared__ float sm[8];
    __shared__ float red_sh;

    float mx = -3.4e38f;
    for (int i = threadIdx.x; i < CV; i += blockDim.x) mx = fmaxf(mx, row[i]);
    for (int o = 16; o > 0; o >>= 1) mx = fmaxf(mx, __shfl_xor_sync(0xffffffffu, mx, o));
    if ((threadIdx.x & 31) == 0) sm[threadIdx.x >> 5] = mx;
    __syncthreads();
    if (threadIdx.x == 0) {
        float t = sm[0]; for (int i = 1; i < 8; i++) t = fmaxf(t, sm[i]);
        red_sh = t;
    }
    __syncthreads();
    mx = red_sh;

    float s = 0.f;
    for (int i = threadIdx.x; i < CV; i += blockDim.x) s += expf(row[i] - mx);
    for (int o = 16; o > 0; o >>= 1) s += __shfl_xor_sync(0xffffffffu, s, o);
    if ((threadIdx.x & 31) == 0) sm[threadIdx.x >> 5] = s;
    __syncthreads();
    if (threadIdx.x == 0) {
        float t = 0.f; for (int i = 0; i < 8; i++) t += sm[i];
        int lab = labels[r];
        if (lab == -100) { nll[r] = 0.f; valid[r] = 0.f; }
        else {
            nll[r] = -(row[lab] - mx - logf(t));
            valid[r] = 1.f;
        }
    }
}

__global__ void loss_final_kernel(const float* __restrict__ nll,
                                  const float* __restrict__ valid,
                                  float* __restrict__ out)
{
    __shared__ float sm[8], sc[8];
    float s = 0.f, c = 0.f;
    for (int i = threadIdx.x; i < CBS; i += blockDim.x) { s += nll[i]; c += valid[i]; }
    for (int o = 16; o > 0; o >>= 1) {
        s += __shfl_xor_sync(0xffffffffu, s, o);
        c += __shfl_xor_sync(0xffffffffu, c, o);
    }
    if ((threadIdx.x & 31) == 0) { sm[threadIdx.x >> 5] = s; sc[threadIdx.x >> 5] = c; }
    __syncthreads();
    if (threadIdx.x == 0) {
        float ts = 0.f, tc = 0.f;
        for (int i = 0; i < 8; i++) { ts += sm[i]; tc += sc[i]; }
        out[0] = ts / fmaxf(tc, 1.f);
    }
}

// ---------------- host orchestration ----------------
extern "C" void kernel_launch(void* const* d_in, const int* in_sizes, int n_in,
                              void* d_out, int out_size)
{
    const int* ids    = (const int*)d_in[0];
    const int* labels = (const int*)d_in[1];
    const float* P[27];
    for (int i = 2; i < 27; i++) P[i] = (const float*)d_in[i];

    const float* emb[2]   = { P[2],  P[14] };
    const float* norm[2]  = { P[3],  P[15] };
    const float* inw[2]   = { P[4],  P[16] };
    const float* convw[2] = { P[5],  P[17] };
    const float* convb[2] = { P[6],  P[18] };
    const float* xpw[2]   = { P[7],  P[19] };
    const float* dtw[2]   = { P[8],  P[20] };
    const float* dtb[2]   = { P[9],  P[21] };
    const float* Alog[2]  = { P[10], P[22] };
    const float* Dp[2]    = { P[11], P[23] };
    const float* outw[2]  = { P[12], P[24] };
    const float* fnorm[2] = { P[13], P[25] };
    const float* lm_w     = P[26];

    float* arena = nullptr;
    cudaGetSymbolAddress((void**)&arena, g_arena);

    float* hB[2]   = { arena + O_H0,   arena + O_H1 };
    float* xnB[2]  = { arena + O_XN0,  arena + O_XN1 };
    float* xzB[2]  = { arena + O_XZ0,  arena + O_XZ1 };
    float* xcB[2]  = { arena + O_XC0,  arena + O_XC1 };
    float* dbcB[2] = { arena + O_DBC0, arena + O_DBC1 };
    float* dtB[2]  = { arena + O_DT0,  arena + O_DT1 };
    float* yB[2]   = { arena + O_Y0,   arena + O_Y1 };
    float* comb    = arena + O_COMB;
    float* nllb    = arena + O_NLL;
    float* valb    = arena + O_VAL;
    float* logits  = (float*)d_out;

    const int EL_THREADS = 256;
    int grid_hdm = (int)(((size_t)CBS * CDM + EL_THREADS - 1) / EL_THREADS);
    int grid_hdi = (int)(((size_t)CBS * CDI + EL_THREADS - 1) / EL_THREADS);

    embed_kernel<<<grid_hdm, EL_THREADS>>>(ids, emb[0], hB[0], 0);
    embed_kernel<<<grid_hdm, EL_THREADS>>>(ids, emb[1], hB[1], 1);

    for (int l = 0; l < CL; l++) {
        for (int dir = 0; dir < 2; dir++) {
            rms_kernel<<<CBS, 256>>>(hB[dir], norm[dir] + (size_t)l * CDM, xnB[dir]);
            // xz = xn @ inw^T : [4096,768] x [3072,768]^T
            gemm_tc<<<dim3((2 * CDI) / BN, CBS / BM), 256>>>(
                xnB[dir], CDM, inw[dir] + (size_t)l * 2 * CDI * CDM,
                xzB[dir], CBS, 2 * CDI, CDM, nullptr, 0, 0);
            conv_kernel<<<grid_hdi, EL_THREADS>>>(
                xzB[dir], convw[dir] + (size_t)l * CDI * CKC,
                convb[dir] + (size_t)l * CDI, xcB[dir]);
            // dbc = xc @ xpw^T : [4096,1536] x [80,1536]^T
            gemm_tc<<<dim3((CDBC + BN - 1) / BN, CBS / BM), 256>>>(
                xcB[dir], CDI, xpw[dir] + (size_t)l * CDBC * CDI,
                dbcB[dir], CBS, CDBC, CDI, nullptr, 0, 0);
            // dt = softplus(dbc[:, :48] @ dtw^T + dtb)
            gemm_tc<<<dim3(CDI / BN, CBS / BM), 256>>>(
                dbcB[dir], CDBC, dtw[dir] + (size_t)l * CDI * CDR,
                dtB[dir], CBS, CDI, CDR, dtb[dir] + (size_t)l * CDI, 1, 0);
            scan_kernel<<<(CB * CDI * 16 + 255) / 256, 256>>>(
                dtB[dir], xcB[dir], dbcB[dir],
                Alog[dir] + (size_t)l * CDI * CDS, yB[dir]);
            gate_kernel<<<grid_hdi, EL_THREADS>>>(
                yB[dir], xcB[dir], xzB[dir], Dp[dir] + (size_t)l * CDI);
            // h += g @ outw^T : [4096,1536] x [768,1536]^T
            gemm_tc<<<dim3(CDM / BN, CBS / BM), 256>>>(
                yB[dir], CDI, outw[dir] + (size_t)l * CDM * CDI,
                hB[dir], CBS, CDM, CDI, nullptr, 0, 1);
        }
    }

    combined_kernel<<<CBS, 256>>>(hB[0], hB[1], fnorm[0], fnorm[1], comb);

    // LM head: logits = comb @ lm_w^T : [4096,1536] x [32000,1536]^T
    gemm_tc<<<dim3(CV / BN, CBS / BM), 256>>>(
        comb, 2 * CDM, lm_w, logits, CBS, CV, 2 * CDM, nullptr, 0, 0);

    loss_row_kernel<<<CBS, 256>>>(logits, labels, nllb, valb);
    loss_final_kernel<<<1, 256>>>(nllb, valb, logits + (out_size - 1));
}